// round 14
// baseline (speedup 1.0000x reference)
#include <cuda_runtime.h>
#include <cstdint>

// CTC forward loss — 2 batch elements (independent alpha chains) per warp,
// 4 lattice states per lane per chain. Interleaving the two serial
// recurrences hides the shfl/LDS latency that bounded the 1-chain kernel.
// Grid 128 x 64thr: exactly one block per SM (2 warps / 2 SMSPs) -> no
// block-count imbalance across SMs.
// Linear-probability domain, power-of-2 renorm every 16 steps (target ~2^64),
// renorm exponent via redux.sync.max.u32 (exact: esum uses applied scale).
// Memory: per-8-row cp.async.cg group pairs (4KB per chain, one commit) into
// 4-deep 16KB rings per chain (64KB dynamic smem per block), wait_group<3>.
#define B_ 512
#define T_ 512
#define C_ 128
#define L_ 48
#define EPS_ 1e-7f

#define GROUP 8
#define NGROUPS (T_ / GROUP)             // 64
#define RING_ROWS 32                     // per-chain ring: 32 rows = 16KB
#define RING_FLOATS (RING_ROWS * C_)     // 4096
#define RING_BYTES  (RING_FLOATS * 4)    // 16384
#define SMEM_TOTAL  (4 * RING_BYTES)     // 64KB (4 chains per block)

extern __shared__ __align__(128) char dsm[];

__global__ __launch_bounds__(64) void ctc_kernel(
    const int* __restrict__ y_true,
    const float* __restrict__ y_pred,
    float* __restrict__ out)
{
    const int lane = threadIdx.x & 31;
    const int warp = threadIdx.x >> 5;          // 0..1
    const unsigned FULL = 0xffffffffu;

    const int b0 = blockIdx.x * 4 + warp * 2;   // chain 0 batch
    const int b1 = b0 + 1;                      // chain 1 batch
    const float* __restrict__ base0 = y_pred + (size_t)b0 * T_ * C_;
    const float* __restrict__ base1 = y_pred + (size_t)b1 * T_ * C_;

    float* ring0f = (float*)dsm + (warp * 2) * RING_FLOATS;
    float* ring1f = ring0f + RING_FLOATS;
    uint32_t ring0_u32, ring1_u32;
    {
        uint64_t t0;
        asm ("cvta.to.shared.u64 %0, %1;" : "=l"(t0) : "l"(ring0f));
        ring0_u32 = (uint32_t)t0 + (uint32_t)(lane << 4);
        ring1_u32 = ring0_u32 + RING_BYTES;
    }

    // ---- lattice wiring per chain: lane l owns states 4l..4l+3 (S=97) ----
    const bool lab = (lane < 24);
    int cls01 = C_ - 1, cls03 = C_ - 1, cls11 = C_ - 1, cls13 = C_ - 1;
    if (lab) {
        cls01 = y_true[b0 * L_ + 2 * lane];
        cls03 = y_true[b0 * L_ + 2 * lane + 1];
        cls11 = y_true[b1 * L_ + 2 * lane];
        cls13 = y_true[b1 * L_ + 2 * lane + 1];
    }
    const int pc03 = __shfl_up_sync(FULL, cls03, 1);
    const int pc13 = __shfl_up_sync(FULL, cls13, 1);
    const float skip01 = (cls01 != pc03) ? 1.f : 0.f;
    const float skip03 = (cls03 != cls01) ? 1.f : 0.f;
    const float skip11 = (cls11 != pc13) ? 1.f : 0.f;
    const float skip13 = (cls13 != cls11) ? 1.f : 0.f;
    const float m0  = (lane <= 24) ? 1.f : 0.f;
    const float m13 = lab ? 1.f : 0.f;

    // issue one group PAIR (8 rows for each chain), single commit
#define ISSUE_PAIR(g_)                                                       \
    do {                                                                     \
        int _r0 = (g_) * GROUP;                                              \
        _Pragma("unroll")                                                    \
        for (int _r = 0; _r < GROUP; ++_r) {                                 \
            int _row = _r0 + _r;                                             \
            uint32_t _off = (uint32_t)((_row & (RING_ROWS - 1)) << 9);       \
            const float* _s0 = base0 + ((size_t)_row << 7) + (lane << 2);    \
            const float* _s1 = base1 + ((size_t)_row << 7) + (lane << 2);    \
            asm volatile("cp.async.cg.shared.global [%0], [%1], 16;"         \
                         :: "r"(ring0_u32 + _off), "l"(_s0) : "memory");     \
            asm volatile("cp.async.cg.shared.global [%0], [%1], 16;"         \
                         :: "r"(ring1_u32 + _off), "l"(_s1) : "memory");     \
        }                                                                    \
        asm volatile("cp.async.commit_group;" ::: "memory");                 \
    } while (0)

#define WAITG(K)                                                             \
    do {                                                                     \
        asm volatile("cp.async.wait_group %0;" :: "n"(K) : "memory");        \
        __syncwarp();                                                        \
    } while (0)

    // one interleaved step for both chains: two independent shfl/flop chains
#define STEP2(pb0, p10, p30, pb1, p11, p31)                                  \
    do {                                                                     \
        float q0 = __shfl_up_sync(FULL, a03, 1);                             \
        float q1 = __shfl_up_sync(FULL, a13, 1);                             \
        if (lane == 0) { q0 = 0.f; q1 = 0.f; }                               \
        float n00 = (a00 + q0) * (pb0);                                      \
        float n01 = ((a01 + a00) + skip01 * q0) * (p10);                     \
        float n02 = (a02 + a01) * (pb0);                                     \
        float n03 = ((a03 + a02) + skip03 * a01) * (p30);                    \
        float n10 = (a10 + q1) * (pb1);                                      \
        float n11 = ((a11 + a10) + skip11 * q1) * (p11);                     \
        float n12 = (a12 + a11) * (pb1);                                     \
        float n13 = ((a13 + a12) + skip13 * a11) * (p31);                    \
        a00 = n00; a01 = n01; a02 = n02; a03 = n03;                          \
        a10 = n10; a11 = n11; a12 = n12; a13 = n13;                          \
    } while (0)

    // per-chain renorm: scale = 2^(191 - e_max), exact power of two
#define RENORM2()                                                            \
    do {                                                                     \
        float w00 = m0 * a00, w01 = m13 * fmaxf(fmaxf(a01, a02), a03);       \
        float w10 = m0 * a10, w11 = m13 * fmaxf(fmaxf(a11, a12), a13);       \
        unsigned wb0 = __float_as_uint(fmaxf(w00, w01));                     \
        unsigned wb1 = __float_as_uint(fmaxf(w10, w11));                     \
        unsigned wm0, wm1;                                                   \
        asm volatile("redux.sync.max.u32 %0, %1, 0xffffffff;"                \
                     : "=r"(wm0) : "r"(wb0));                                \
        asm volatile("redux.sync.max.u32 %0, %1, 0xffffffff;"                \
                     : "=r"(wm1) : "r"(wb1));                                \
        int e0 = (int)(wm0 >> 23) & 255;                                     \
        int e1 = (int)(wm1 >> 23) & 255;                                     \
        int f0_ = 318 - e0; f0_ = (f0_ > 254) ? 254 : f0_;                   \
        int f1_ = 318 - e1; f1_ = (f1_ > 254) ? 254 : f1_;                   \
        float s0 = __int_as_float(f0_ << 23);                                \
        float s1 = __int_as_float(f1_ << 23);                                \
        a00 *= s0; a01 *= s0; a02 *= s0; a03 *= s0;                          \
        a10 *= s1; a11 *= s1; a12 *= s1; a13 *= s1;                          \
        esum0 -= (float)(f0_ - 127);                                         \
        esum1 -= (float)(f1_ - 127);                                         \
    } while (0)

#define CONSUME8(g_)                                                         \
    do {                                                                     \
        int _r0 = (g_) * GROUP;                                              \
        _Pragma("unroll")                                                    \
        for (int _u = 0; _u < GROUP; ++_u) {                                 \
            const float* _c0 = ring0f + (((_r0 + _u) & (RING_ROWS - 1)) * C_); \
            const float* _c1 = ring1f + (((_r0 + _u) & (RING_ROWS - 1)) * C_); \
            float _pb0 = _c0[C_ - 1] + EPS_;                                 \
            float _p10 = _c0[cls01] + EPS_;                                  \
            float _p30 = _c0[cls03] + EPS_;                                  \
            float _pb1 = _c1[C_ - 1] + EPS_;                                 \
            float _p11 = _c1[cls11] + EPS_;                                  \
            float _p31 = _c1[cls13] + EPS_;                                  \
            STEP2(_pb0, _p10, _p30, _pb1, _p11, _p31);                       \
        }                                                                    \
    } while (0)

    float a00 = 0.f, a01 = 0.f, a02 = 0.f, a03 = 0.f;
    float a10 = 0.f, a11 = 0.f, a12 = 0.f, a13 = 0.f;
    float esum0 = 0.f, esum1 = 0.f;

    // ---- prologue: issue group pairs 0..3 (ring full, 32KB/warp in flight) ----
#pragma unroll
    for (int g = 0; g < 4; ++g) ISSUE_PAIR(g);

    // ---- group 0: t=0 init + steps t=1..7 ----
    {
        WAITG(3);
        float pb00 = ring0f[C_ - 1] + EPS_, pl00 = ring0f[cls01] + EPS_;
        float pb10 = ring1f[C_ - 1] + EPS_, pl10 = ring1f[cls11] + EPS_;
        if (lane == 0) { a00 = pb00; a01 = pl00; a10 = pb10; a11 = pl10; }
#pragma unroll
        for (int t = 1; t < GROUP; ++t) {
            const float* c0 = ring0f + t * C_;
            const float* c1 = ring1f + t * C_;
            float pb0 = c0[C_ - 1] + EPS_, p10 = c0[cls01] + EPS_, p30 = c0[cls03] + EPS_;
            float pb1 = c1[C_ - 1] + EPS_, p11 = c1[cls11] + EPS_, p31 = c1[cls13] + EPS_;
            STEP2(pb0, p10, p30, pb1, p11, p31);
        }
        ISSUE_PAIR(4);
    }

    // ---- main loop: g = 1..59, issue g+4 (covers 5..63) ----
    for (int g = 1; g <= 59; ++g) {
        WAITG(3);
        CONSUME8(g);
        if (g & 1) RENORM2();                 // after t = 16k+15
        ISSUE_PAIR(g + 4);
    }

    // ---- tail: g = 60..63, decreasing waits ----
#define TAILG(g_, K_)                                                        \
    do { WAITG(K_); CONSUME8(g_); if ((g_) & 1) RENORM2(); } while (0)
    TAILG(60, 3);
    TAILG(61, 2);
    TAILG(62, 1);
    TAILG(63, 0);
#undef TAILG

    // ---- final: -log(alpha[S-1] + alpha[S-2]) - esum*ln2, per chain ----
    float f00 = __shfl_sync(FULL, a00, 24);   // state 96
    float f01 = __shfl_sync(FULL, a03, 23);   // state 95
    float f10 = __shfl_sync(FULL, a10, 24);
    float f11 = __shfl_sync(FULL, a13, 23);
    if (lane == 0) {
        out[b0] = -(logf(f00 + f01) + esum0 * 0.69314718055994531f);
        out[b1] = -(logf(f10 + f11) + esum1 * 0.69314718055994531f);
    }

#undef STEP2
#undef RENORM2
#undef CONSUME8
#undef ISSUE_PAIR
#undef WAITG
}

extern "C" void kernel_launch(void* const* d_in, const int* in_sizes, int n_in,
                              void* d_out, int out_size)
{
    const int*   y_true = (const int*)d_in[0];    // [512, 48] int32
    const float* y_pred = (const float*)d_in[1];  // [512, 512, 128] float32
    float*       out    = (float*)d_out;          // [512, 1] float32
    (void)in_sizes; (void)n_in; (void)out_size;

    cudaFuncSetAttribute(ctc_kernel,
                         cudaFuncAttributeMaxDynamicSharedMemorySize,
                         SMEM_TOTAL);
    ctc_kernel<<<B_ / 4, 64, SMEM_TOTAL>>>(y_true, y_pred, out);
}

// round 15
// speedup vs baseline: 1.0021x; 1.0021x over previous
#include <cuda_runtime.h>
#include <cstdint>

// CTC forward loss — one batch element (alpha chain) per warp, 4 lattice
// states per lane. 128 blocks x 128 threads: one block per SM, 4 warps on
// 4 SMSPs (1 warp each), 1 chain per warp -> balanced across SMs AND SMSPs
// (R12 had a 4-vs-3 block/SM tail; R14 concentrated issue on 2 SMSPs).
// Linear-probability domain, power-of-2 renorm every 16 steps (target ~2^64),
// renorm exponent via redux.sync.max.u32 (exact: esum uses applied scale).
// Memory: per-8-row cp.async.cg groups (4KB, lane copies 16B -> warp covers
// the 512B row) into a private 32-row (16KB) ring per warp, wait_group<3>.
#define B_ 512
#define T_ 512
#define C_ 128
#define L_ 48
#define EPS_ 1e-7f

#define GROUP 8
#define NGROUPS (T_ / GROUP)             // 64
#define RING_ROWS 32                     // per-warp ring: 32 rows = 16KB
#define RING_FLOATS (RING_ROWS * C_)     // 4096
#define RING_BYTES  (RING_FLOATS * 4)    // 16384
#define SMEM_TOTAL  (4 * RING_BYTES)     // 64KB (4 warps per block)

extern __shared__ __align__(128) char dsm[];

__global__ __launch_bounds__(128) void ctc_kernel(
    const int* __restrict__ y_true,
    const float* __restrict__ y_pred,
    float* __restrict__ out)
{
    const int lane = threadIdx.x & 31;
    const int warp = threadIdx.x >> 5;          // 0..3
    const unsigned FULL = 0xffffffffu;

    const int b = blockIdx.x * 4 + warp;        // this warp's batch element
    const float* __restrict__ base = y_pred + (size_t)b * T_ * C_;

    float* ringf = (float*)dsm + warp * RING_FLOATS;
    uint32_t ring_u32;
    {
        uint64_t t0;
        asm ("cvta.to.shared.u64 %0, %1;" : "=l"(t0) : "l"(ringf));
        ring_u32 = (uint32_t)t0 + (uint32_t)(lane << 4);   // lane's 16B slot
    }

    // ---- lattice wiring: lane l owns states 4l..4l+3 (S = 97) ----
    const bool lab = (lane < 24);
    int cls1 = C_ - 1, cls3 = C_ - 1;
    if (lab) {
        cls1 = y_true[b * L_ + 2 * lane];
        cls3 = y_true[b * L_ + 2 * lane + 1];
    }
    const int prev_cls3 = __shfl_up_sync(FULL, cls3, 1);
    const float skip1 = (cls1 != prev_cls3) ? 1.f : 0.f;
    const float skip3 = (cls3 != cls1)      ? 1.f : 0.f;
    const float m0  = (lane <= 24) ? 1.f : 0.f;
    const float m13 = lab ? 1.f : 0.f;

    // issue one 8-row group (4KB), then commit
#define ISSUE_GROUP(g_)                                                      \
    do {                                                                     \
        int _r0 = (g_) * GROUP;                                              \
        _Pragma("unroll")                                                    \
        for (int _r = 0; _r < GROUP; ++_r) {                                 \
            int _row = _r0 + _r;                                             \
            uint32_t _dst = ring_u32 + (uint32_t)((_row & (RING_ROWS-1)) << 9); \
            const float* _src = base + ((size_t)_row << 7) + (lane << 2);    \
            asm volatile("cp.async.cg.shared.global [%0], [%1], 16;"         \
                         :: "r"(_dst), "l"(_src) : "memory");                \
        }                                                                    \
        asm volatile("cp.async.commit_group;" ::: "memory");                 \
    } while (0)

#define WAITG(K)                                                             \
    do {                                                                     \
        asm volatile("cp.async.wait_group %0;" :: "n"(K) : "memory");        \
        __syncwarp();                                                        \
    } while (0)

#define STEP(pb, pl1, pl3)                                                   \
    do {                                                                     \
        float q = __shfl_up_sync(FULL, a3, 1);                               \
        if (lane == 0) q = 0.f;                                              \
        float n0 = (a0 + q) * (pb);                                          \
        float n1 = ((a1 + a0) + skip1 * q) * (pl1);                          \
        float n2 = (a2 + a1) * (pb);                                         \
        float n3 = ((a3 + a2) + skip3 * a1) * (pl3);                         \
        a0 = n0; a1 = n1; a2 = n2; a3 = n3;                                  \
    } while (0)

    // Renorm: scale = 2^(191 - e_max), exact power of two.
#define RENORM()                                                             \
    do {                                                                     \
        float w0 = m0 * a0;                                                  \
        float w1 = m13 * fmaxf(fmaxf(a1, a2), a3);                           \
        unsigned wb = __float_as_uint(fmaxf(w0, w1));                        \
        unsigned wm;                                                         \
        asm volatile("redux.sync.max.u32 %0, %1, 0xffffffff;"                \
                     : "=r"(wm) : "r"(wb));                                  \
        int e = (int)(wm >> 23) & 255;                                       \
        int f = 318 - e;                                                     \
        f = (f > 254) ? 254 : f;                                             \
        float scale = __int_as_float(f << 23);                               \
        a0 *= scale; a1 *= scale; a2 *= scale; a3 *= scale;                  \
        esum -= (float)(f - 127);                                            \
    } while (0)

#define CONSUME8(g_)                                                         \
    do {                                                                     \
        int _r0 = (g_) * GROUP;                                              \
        _Pragma("unroll")                                                    \
        for (int _u = 0; _u < GROUP; ++_u) {                                 \
            const float* _rp = ringf + (((_r0 + _u) & (RING_ROWS-1)) * C_);  \
            float _pb = _rp[C_ - 1] + EPS_;                                  \
            float _p1 = _rp[cls1] + EPS_;                                    \
            float _p3 = _rp[cls3] + EPS_;                                    \
            STEP(_pb, _p1, _p3);                                             \
        }                                                                    \
    } while (0)

    float a0 = 0.f, a1 = 0.f, a2 = 0.f, a3 = 0.f;
    float esum = 0.f;

    // ---- prologue: issue groups 0..3 (ring full, 16KB in flight) ----
#pragma unroll
    for (int g = 0; g < 4; ++g) ISSUE_GROUP(g);

    // ---- group 0: t=0 init + steps t=1..7 ----
    {
        WAITG(3);
        float pb0 = ringf[C_ - 1] + EPS_;
        float pl0 = ringf[cls1] + EPS_;
        if (lane == 0) { a0 = pb0; a1 = pl0; }
#pragma unroll
        for (int t = 1; t < GROUP; ++t) {
            const float* r = ringf + t * C_;
            float pb = r[C_ - 1] + EPS_;
            float p1 = r[cls1] + EPS_;
            float p3 = r[cls3] + EPS_;
            STEP(pb, p1, p3);
        }
        ISSUE_GROUP(4);
    }

    // ---- main loop: g = 1..59, issue g+4 (covers 5..63) ----
    for (int g = 1; g <= 59; ++g) {
        WAITG(3);
        CONSUME8(g);
        if (g & 1) RENORM();                  // after t = 16k+15
        ISSUE_GROUP(g + 4);
    }

    // ---- tail: g = 60..63, decreasing waits ----
#define TAILG(g_, K_)                                                        \
    do { WAITG(K_); CONSUME8(g_); if ((g_) & 1) RENORM(); } while (0)
    TAILG(60, 3);
    TAILG(61, 2);
    TAILG(62, 1);
    TAILG(63, 0);
#undef TAILG

    // ---- final: -log(alpha[S-1] + alpha[S-2]) - esum*ln2 ----
    float f0 = __shfl_sync(FULL, a0, 24);   // state 96 (final blank)
    float f1 = __shfl_sync(FULL, a3, 23);   // state 95 (last label)
    if (lane == 0)
        out[b] = -(logf(f0 + f1) + esum * 0.69314718055994531f);

#undef STEP
#undef RENORM
#undef CONSUME8
#undef ISSUE_GROUP
#undef WAITG
}

extern "C" void kernel_launch(void* const* d_in, const int* in_sizes, int n_in,
                              void* d_out, int out_size)
{
    const int*   y_true = (const int*)d_in[0];    // [512, 48] int32
    const float* y_pred = (const float*)d_in[1];  // [512, 512, 128] float32
    float*       out    = (float*)d_out;          // [512, 1] float32
    (void)in_sizes; (void)n_in; (void)out_size;

    cudaFuncSetAttribute(ctc_kernel,
                         cudaFuncAttributeMaxDynamicSharedMemorySize,
                         SMEM_TOTAL);
    ctc_kernel<<<B_ / 4, 128, SMEM_TOTAL>>>(y_true, y_pred, out);
}

// round 16
// speedup vs baseline: 1.0095x; 1.0074x over previous
#include <cuda_runtime.h>
#include <cstdint>

// CTC forward loss — 2 batch elements (independent alpha chains) per warp,
// 4 lattice states per lane per chain; ONE warp per block, 256 blocks spread
// over all 148 SMs. The 2-chain interleave halves per-element serial latency
// (proven in R14); single-warp blocks restore the 148-SM spread (proven in
// R12). Linear-probability domain, power-of-2 renorm every 16 steps
// (target ~2^64), renorm exponent via redux.sync.max.u32.
// Memory: per-8-row cp.async.cg group pairs (4KB per chain, one commit) into
// 4-deep 16KB rings per chain (32KB dynamic smem per block), wait_group<3>.
#define B_ 512
#define T_ 512
#define C_ 128
#define L_ 48
#define EPS_ 1e-7f

#define GROUP 8
#define NGROUPS (T_ / GROUP)             // 64
#define RING_ROWS 32                     // per-chain ring: 32 rows = 16KB
#define RING_FLOATS (RING_ROWS * C_)     // 4096
#define RING_BYTES  (RING_FLOATS * 4)    // 16384
#define SMEM_TOTAL  (2 * RING_BYTES)     // 32KB (2 chains per block)

extern __shared__ __align__(128) char dsm[];

__global__ __launch_bounds__(32) void ctc_kernel(
    const int* __restrict__ y_true,
    const float* __restrict__ y_pred,
    float* __restrict__ out)
{
    const int lane = threadIdx.x & 31;
    const unsigned FULL = 0xffffffffu;

    const int b0 = blockIdx.x * 2;              // chain 0 batch
    const int b1 = b0 + 1;                      // chain 1 batch
    const float* __restrict__ base0 = y_pred + (size_t)b0 * T_ * C_;
    const float* __restrict__ base1 = y_pred + (size_t)b1 * T_ * C_;

    float* ring0f = (float*)dsm;
    float* ring1f = ring0f + RING_FLOATS;
    uint32_t ring0_u32, ring1_u32;
    {
        uint64_t t0;
        asm ("cvta.to.shared.u64 %0, %1;" : "=l"(t0) : "l"(ring0f));
        ring0_u32 = (uint32_t)t0 + (uint32_t)(lane << 4);
        ring1_u32 = ring0_u32 + RING_BYTES;
    }

    // ---- lattice wiring per chain: lane l owns states 4l..4l+3 (S=97) ----
    const bool lab = (lane < 24);
    int cls01 = C_ - 1, cls03 = C_ - 1, cls11 = C_ - 1, cls13 = C_ - 1;
    if (lab) {
        cls01 = y_true[b0 * L_ + 2 * lane];
        cls03 = y_true[b0 * L_ + 2 * lane + 1];
        cls11 = y_true[b1 * L_ + 2 * lane];
        cls13 = y_true[b1 * L_ + 2 * lane + 1];
    }
    const int pc03 = __shfl_up_sync(FULL, cls03, 1);
    const int pc13 = __shfl_up_sync(FULL, cls13, 1);
    const float skip01 = (cls01 != pc03) ? 1.f : 0.f;
    const float skip03 = (cls03 != cls01) ? 1.f : 0.f;
    const float skip11 = (cls11 != pc13) ? 1.f : 0.f;
    const float skip13 = (cls13 != cls11) ? 1.f : 0.f;
    const float m0  = (lane <= 24) ? 1.f : 0.f;
    const float m13 = lab ? 1.f : 0.f;

    // issue one group PAIR (8 rows for each chain), single commit
#define ISSUE_PAIR(g_)                                                       \
    do {                                                                     \
        int _r0 = (g_) * GROUP;                                              \
        _Pragma("unroll")                                                    \
        for (int _r = 0; _r < GROUP; ++_r) {                                 \
            int _row = _r0 + _r;                                             \
            uint32_t _off = (uint32_t)((_row & (RING_ROWS - 1)) << 9);       \
            const float* _s0 = base0 + ((size_t)_row << 7) + (lane << 2);    \
            const float* _s1 = base1 + ((size_t)_row << 7) + (lane << 2);    \
            asm volatile("cp.async.cg.shared.global [%0], [%1], 16;"         \
                         :: "r"(ring0_u32 + _off), "l"(_s0) : "memory");     \
            asm volatile("cp.async.cg.shared.global [%0], [%1], 16;"         \
                         :: "r"(ring1_u32 + _off), "l"(_s1) : "memory");     \
        }                                                                    \
        asm volatile("cp.async.commit_group;" ::: "memory");                 \
    } while (0)

#define WAITG(K)                                                             \
    do {                                                                     \
        asm volatile("cp.async.wait_group %0;" :: "n"(K) : "memory");        \
        __syncwarp();                                                        \
    } while (0)

    // one interleaved step for both chains: two independent shfl/flop chains
#define STEP2(pb0, p10, p30, pb1, p11, p31)                                  \
    do {                                                                     \
        float q0 = __shfl_up_sync(FULL, a03, 1);                             \
        float q1 = __shfl_up_sync(FULL, a13, 1);                             \
        if (lane == 0) { q0 = 0.f; q1 = 0.f; }                               \
        float n00 = (a00 + q0) * (pb0);                                      \
        float n01 = ((a01 + a00) + skip01 * q0) * (p10);                     \
        float n02 = (a02 + a01) * (pb0);                                     \
        float n03 = ((a03 + a02) + skip03 * a01) * (p30);                    \
        float n10 = (a10 + q1) * (pb1);                                      \
        float n11 = ((a11 + a10) + skip11 * q1) * (p11);                     \
        float n12 = (a12 + a11) * (pb1);                                     \
        float n13 = ((a13 + a12) + skip13 * a11) * (p31);                    \
        a00 = n00; a01 = n01; a02 = n02; a03 = n03;                          \
        a10 = n10; a11 = n11; a12 = n12; a13 = n13;                          \
    } while (0)

    // per-chain renorm: scale = 2^(191 - e_max), exact power of two
#define RENORM2()                                                            \
    do {                                                                     \
        float w00 = m0 * a00, w01 = m13 * fmaxf(fmaxf(a01, a02), a03);       \
        float w10 = m0 * a10, w11 = m13 * fmaxf(fmaxf(a11, a12), a13);       \
        unsigned wb0 = __float_as_uint(fmaxf(w00, w01));                     \
        unsigned wb1 = __float_as_uint(fmaxf(w10, w11));                     \
        unsigned wm0, wm1;                                                   \
        asm volatile("redux.sync.max.u32 %0, %1, 0xffffffff;"                \
                     : "=r"(wm0) : "r"(wb0));                                \
        asm volatile("redux.sync.max.u32 %0, %1, 0xffffffff;"                \
                     : "=r"(wm1) : "r"(wb1));                                \
        int e0 = (int)(wm0 >> 23) & 255;                                     \
        int e1 = (int)(wm1 >> 23) & 255;                                     \
        int f0_ = 318 - e0; f0_ = (f0_ > 254) ? 254 : f0_;                   \
        int f1_ = 318 - e1; f1_ = (f1_ > 254) ? 254 : f1_;                   \
        float s0 = __int_as_float(f0_ << 23);                                \
        float s1 = __int_as_float(f1_ << 23);                                \
        a00 *= s0; a01 *= s0; a02 *= s0; a03 *= s0;                          \
        a10 *= s1; a11 *= s1; a12 *= s1; a13 *= s1;                          \
        esum0 -= (float)(f0_ - 127);                                         \
        esum1 -= (float)(f1_ - 127);                                         \
    } while (0)

#define CONSUME8(g_)                                                         \
    do {                                                                     \
        int _r0 = (g_) * GROUP;                                              \
        _Pragma("unroll")                                                    \
        for (int _u = 0; _u < GROUP; ++_u) {                                 \
            const float* _c0 = ring0f + (((_r0 + _u) & (RING_ROWS - 1)) * C_); \
            const float* _c1 = ring1f + (((_r0 + _u) & (RING_ROWS - 1)) * C_); \
            float _pb0 = _c0[C_ - 1] + EPS_;                                 \
            float _p10 = _c0[cls01] + EPS_;                                  \
            float _p30 = _c0[cls03] + EPS_;                                  \
            float _pb1 = _c1[C_ - 1] + EPS_;                                 \
            float _p11 = _c1[cls11] + EPS_;                                  \
            float _p31 = _c1[cls13] + EPS_;                                  \
            STEP2(_pb0, _p10, _p30, _pb1, _p11, _p31);                       \
        }                                                                    \
    } while (0)

    float a00 = 0.f, a01 = 0.f, a02 = 0.f, a03 = 0.f;
    float a10 = 0.f, a11 = 0.f, a12 = 0.f, a13 = 0.f;
    float esum0 = 0.f, esum1 = 0.f;

    // ---- prologue: issue group pairs 0..3 (rings full, 32KB in flight) ----
#pragma unroll
    for (int g = 0; g < 4; ++g) ISSUE_PAIR(g);

    // ---- group 0: t=0 init + steps t=1..7 ----
    {
        WAITG(3);
        float pb00 = ring0f[C_ - 1] + EPS_, pl00 = ring0f[cls01] + EPS_;
        float pb10 = ring1f[C_ - 1] + EPS_, pl10 = ring1f[cls11] + EPS_;
        if (lane == 0) { a00 = pb00; a01 = pl00; a10 = pb10; a11 = pl10; }
#pragma unroll
        for (int t = 1; t < GROUP; ++t) {
            const float* c0 = ring0f + t * C_;
            const float* c1 = ring1f + t * C_;
            float pb0 = c0[C_ - 1] + EPS_, p10 = c0[cls01] + EPS_, p30 = c0[cls03] + EPS_;
            float pb1 = c1[C_ - 1] + EPS_, p11 = c1[cls11] + EPS_, p31 = c1[cls13] + EPS_;
            STEP2(pb0, p10, p30, pb1, p11, p31);
        }
        ISSUE_PAIR(4);
    }

    // ---- main loop: g = 1..59, issue g+4 (covers 5..63) ----
    for (int g = 1; g <= 59; ++g) {
        WAITG(3);
        CONSUME8(g);
        if (g & 1) RENORM2();                 // after t = 16k+15
        ISSUE_PAIR(g + 4);
    }

    // ---- tail: g = 60..63, decreasing waits ----
#define TAILG(g_, K_)                                                        \
    do { WAITG(K_); CONSUME8(g_); if ((g_) & 1) RENORM2(); } while (0)
    TAILG(60, 3);
    TAILG(61, 2);
    TAILG(62, 1);
    TAILG(63, 0);
#undef TAILG

    // ---- final: -log(alpha[S-1] + alpha[S-2]) - esum*ln2, per chain ----
    float f00 = __shfl_sync(FULL, a00, 24);   // state 96
    float f01 = __shfl_sync(FULL, a03, 23);   // state 95
    float f10 = __shfl_sync(FULL, a10, 24);
    float f11 = __shfl_sync(FULL, a13, 23);
    if (lane == 0) {
        out[b0] = -(logf(f00 + f01) + esum0 * 0.69314718055994531f);
        out[b1] = -(logf(f10 + f11) + esum1 * 0.69314718055994531f);
    }

#undef STEP2
#undef RENORM2
#undef CONSUME8
#undef ISSUE_PAIR
#undef WAITG
}

extern "C" void kernel_launch(void* const* d_in, const int* in_sizes, int n_in,
                              void* d_out, int out_size)
{
    const int*   y_true = (const int*)d_in[0];    // [512, 48] int32
    const float* y_pred = (const float*)d_in[1];  // [512, 512, 128] float32
    float*       out    = (float*)d_out;          // [512, 1] float32
    (void)in_sizes; (void)n_in; (void)out_size;

    cudaFuncSetAttribute(ctc_kernel,
                         cudaFuncAttributeMaxDynamicSharedMemorySize,
                         SMEM_TOTAL);
    ctc_kernel<<<B_ / 2, 32, SMEM_TOTAL>>>(y_true, y_pred, out);
}